// round 9
// baseline (speedup 1.0000x reference)
#include <cuda_runtime.h>

// QPSK modulator: bits (256,16384) int32 -> Gray QPSK -> x16 zero-stuff
// (offset 8) -> RRC (K=128) -> out (256, 131072, 2) float32.
//
// Polyphase: y[16q+p] = sum_{i=0..7} sym[q+jmin+i] * rrc[k0+16i],
//   k0 = (71-p)&15, jmin = (p<=7) ? -4 : -3, scaled by sqrt(16).
// Symbols are +-1/sqrt2 -> each output is a sum of 8 signed taps -> 256
// values per phase. Within a phase QUAD (p0 in {0,4,8,12}) the symbol
// window, flag and sign pattern are identical -> table T4[quad][pattern]
// of float4 gives 4 phases per LDS.128. Mainloop: ballot sign bits ->
// funnel-shift pattern -> 2x LDS.128 -> 2x streaming STG.128 (4 complex).
// R9 = R7 (41.4us champion: .cs stores, non-persistent, fixup barrier)
// with the quad-float4 table; half the loop trips / lookup instructions.

#define B_ROWS     256
#define NUM_BITS   16384
#define NS         8192
#define SPS        16
#define UP_LEN     (NS * SPS)          // 131072
#define SCALE      2.82842712474619f   // sqrt(16)/sqrt(2)

#define SYMS_PER_BLOCK   512
#define OUTS_PER_BLOCK   (SYMS_PER_BLOCK * SPS)     // 8192 complex
#define THREADS          256
#define ITS              8
#define TILES            (UP_LEN / OUTS_PER_BLOCK)  // 16
#define TROW4            257                        // padded row stride (float4)
#define NWORDS           18                         // 520 sign bits

typedef unsigned long long ull;

__device__ __forceinline__ ull pack2(float lo, float hi) {
    ull v;
    asm("mov.b64 %0, {%1, %2};" : "=l"(v) : "f"(lo), "f"(hi));
    return v;
}

__device__ __forceinline__ void stcs2(ulonglong2* p, ull lo, ull hi) {
    asm volatile("st.global.cs.v2.u64 [%0], {%1, %2};"
                 :: "l"(p), "l"(lo), "l"(hi) : "memory");
}

__device__ __forceinline__ void stcs1(ull* p, ull v) {
    asm volatile("st.global.cs.u64 [%0], %1;" :: "l"(p), "l"(v) : "memory");
}

__global__ __launch_bounds__(THREADS, 8)
void qpsk_mod_kernel(const int* __restrict__ bits,
                     const float* __restrict__ rrc,
                     ulonglong2* __restrict__ out4)
{
    __shared__ __align__(16) float4 s_tab[4 * TROW4];
    __shared__ unsigned s_wre[NWORDS], s_wim[NWORDS];

    const int tid  = threadIdx.x;
    const int tile = blockIdx.x;       // 0..15
    const int row  = blockIdx.y;       // 0..255
    const int q0   = tile * SYMS_PER_BLOCK;

    // ---- Build quad table: thread group (tid>>6) fills quad row, entries
    // (tid&63) + 64j. Taps load as warp-wide LDG broadcasts.
    {
        const int qd   = tid >> 6;          // quad row 0..3 -> phases 4qd..4qd+3
        const int ent0 = tid & 63;
        float t[4][8];
        #pragma unroll
        for (int d = 0; d < 4; d++) {
            int k0 = (71 - (4 * qd + d)) & 15;
            #pragma unroll
            for (int i = 0; i < 8; i++)
                t[d][i] = __ldg(rrc + k0 + 16 * i) * SCALE;
        }
        #pragma unroll
        for (int j = 0; j < 4; j++) {
            int b = ent0 + 64 * j;
            float v[4] = {0.f, 0.f, 0.f, 0.f};
            #pragma unroll
            for (int i = 0; i < 8; i++) {
                float sg = ((b >> i) & 1) ? -1.f : 1.f;
                #pragma unroll
                for (int d = 0; d < 4; d++)
                    v[d] = fmaf(sg, t[d][i], v[d]);
            }
            s_tab[qd * TROW4 + b] = make_float4(v[0], v[1], v[2], v[3]);
        }
    }

    // ---- Stage sign bits via ballot: word w holds symbols 32w..32w+31
    // (local t <-> symbol g = q0-4+t; out-of-range -> +1, fixed up below).
    const int2* bits2 = (const int2*)(bits + (long long)row * NUM_BITS);
    const unsigned lane = tid & 31;
    #pragma unroll
    for (int k = 0; k < 3; k++) {
        int t = k * THREADS + tid;
        int g = q0 - 4 + t;
        bool valid = (t < SYMS_PER_BLOCK + 8) && (g >= 0) && (g < NS);
        int2 bb = make_int2(0, 0);
        if (valid) bb = bits2[g];
        unsigned mre = __ballot_sync(0xFFFFFFFFu, valid && (bb.y & 1));
        unsigned mim = __ballot_sync(0xFFFFFFFFu, valid && (bb.x & 1));
        int wi = t >> 5;
        if (lane == 0 && wi < NWORDS) { s_wre[wi] = mre; s_wim[wi] = mim; }
    }
    __syncthreads();

    // ---- Main loop: fixed phase quad (4l..4l+3) per thread.
    const int l    = tid & 3;
    const int grp  = tid >> 2;                 // 0..63 (symbol slot within step)
    const int flag = (l >= 2) ? 1 : 0;         // (phase >= 8)
    const float4* tabp = s_tab + l * TROW4;
    ulonglong2* out_base =
        out4 + (((long long)row * UP_LEN + (long long)tile * OUTS_PER_BLOCK) >> 1);

    #pragma unroll
    for (int it = 0; it < ITS; it++) {
        int s  = it * 64 + grp;                // symbol slot 0..511
        int w  = s + flag;                     // window start bit
        int wi = w >> 5, sh = w & 31;
        unsigned pre = __funnelshift_r(s_wre[wi], s_wre[wi + 1], sh) & 0xFF;
        unsigned pim = __funnelshift_r(s_wim[wi], s_wim[wi + 1], sh) & 0xFF;
        float4 vr = tabp[pre];                 // re for phases 4l..4l+3
        float4 vi = tabp[pim];                 // im for phases 4l..4l+3
        ulonglong2* dst = out_base + s * 8 + 2 * l;   // 4 consecutive complex
        stcs2(dst,     pack2(vr.x, vi.x), pack2(vr.y, vi.y));
        stcs2(dst + 1, pack2(vr.z, vi.z), pack2(vr.w, vi.w));
    }

    // ---- Edge fixup: windows touching symbols outside [0,NS) assumed +1;
    // true value uses 0. Contaminated: n<64 and n>=UP_LEN-64. Recompute.
    // Barrier orders fixup stores after mainloop stores (R8 lesson).
    if (tile == 0 || tile == TILES - 1) {
        __syncthreads();
        if (tid < 64) {
            int n = (tile == 0) ? tid : (UP_LEN - 64 + tid);
            int p = n & 15, q = n >> 4;
            int k0   = (71 - p) & 15;
            int jmin = (p <= 7) ? -4 : -3;
            float re = 0.f, im = 0.f;
            #pragma unroll
            for (int i = 0; i < 8; i++) {
                int g = q + jmin + i;
                if ((unsigned)g < (unsigned)NS) {
                    int2 bb = bits2[g];
                    float t = __ldg(rrc + k0 + 16 * i) * SCALE;
                    re += (bb.y & 1) ? -t : t;
                    im += (bb.x & 1) ? -t : t;
                }
            }
            ull* out2 = (ull*)out4;
            stcs1(out2 + (long long)row * UP_LEN + n, pack2(re, im));
        }
    }
}

extern "C" void kernel_launch(void* const* d_in, const int* in_sizes, int n_in,
                              void* d_out, int out_size)
{
    const int*   bits = (const int*)d_in[0];
    const float* rrc  = (const float*)d_in[1];
    ulonglong2*  out  = (ulonglong2*)d_out;

    dim3 grid(TILES, B_ROWS);                 // (16, 256)
    qpsk_mod_kernel<<<grid, THREADS>>>(bits, rrc, out);
}

// round 10
// speedup vs baseline: 1.6013x; 1.6013x over previous
#include <cuda_runtime.h>

// QPSK modulator: bits (256,16384) int32 -> Gray QPSK -> x16 zero-stuff
// (offset 8) -> RRC (K=128) -> out (256, 131072, 2) float32.
//
// Polyphase: y[16q+p] = sum_{i=0..7} sym[q+jmin+i] * rrc[k0+16i],
//   k0 = (71-p)&15, jmin = (p<=7) ? -4 : -3, scaled by sqrt(16).
// Symbols are +-1/sqrt2 -> each output is a sum of 8 signed taps -> 256
// values per phase. Within a phase QUAD (p0 in {0,4,8,12}) the symbol
// window, flag and sign pattern are identical -> table T4[quad][pattern]
// of float4 gives 4 phases per LDS.128. Mainloop: ballot sign bits ->
// funnel-shift pattern -> 2x LDS.128 -> 2x streaming STG.128 (4 complex).
// R9 = R7 (41.4us champion: .cs stores, non-persistent, fixup barrier)
// with the quad-float4 table; half the loop trips / lookup instructions.

#define B_ROWS     256
#define NUM_BITS   16384
#define NS         8192
#define SPS        16
#define UP_LEN     (NS * SPS)          // 131072
#define SCALE      2.82842712474619f   // sqrt(16)/sqrt(2)

#define SYMS_PER_BLOCK   512
#define OUTS_PER_BLOCK   (SYMS_PER_BLOCK * SPS)     // 8192 complex
#define THREADS          256
#define ITS              8
#define TILES            (UP_LEN / OUTS_PER_BLOCK)  // 16
#define TROW4            257                        // padded row stride (float4)
#define NWORDS           18                         // 520 sign bits

typedef unsigned long long ull;

__device__ __forceinline__ ull pack2(float lo, float hi) {
    ull v;
    asm("mov.b64 %0, {%1, %2};" : "=l"(v) : "f"(lo), "f"(hi));
    return v;
}

__device__ __forceinline__ void stcs2(ulonglong2* p, ull lo, ull hi) {
    asm volatile("st.global.cs.v2.u64 [%0], {%1, %2};"
                 :: "l"(p), "l"(lo), "l"(hi) : "memory");
}

__device__ __forceinline__ void stcs1(ull* p, ull v) {
    asm volatile("st.global.cs.u64 [%0], %1;" :: "l"(p), "l"(v) : "memory");
}

__global__ __launch_bounds__(THREADS, 8)
void qpsk_mod_kernel(const int* __restrict__ bits,
                     const float* __restrict__ rrc,
                     ulonglong2* __restrict__ out4)
{
    __shared__ __align__(16) float4 s_tab[4 * TROW4];
    __shared__ unsigned s_wre[NWORDS], s_wim[NWORDS];

    const int tid  = threadIdx.x;
    const int tile = blockIdx.x;       // 0..15
    const int row  = blockIdx.y;       // 0..255
    const int q0   = tile * SYMS_PER_BLOCK;

    // ---- Build quad table: thread group (tid>>6) fills quad row, entries
    // (tid&63) + 64j. Taps load as warp-wide LDG broadcasts.
    {
        const int qd   = tid >> 6;          // quad row 0..3 -> phases 4qd..4qd+3
        const int ent0 = tid & 63;
        float t[4][8];
        #pragma unroll
        for (int d = 0; d < 4; d++) {
            int k0 = (71 - (4 * qd + d)) & 15;
            #pragma unroll
            for (int i = 0; i < 8; i++)
                t[d][i] = __ldg(rrc + k0 + 16 * i) * SCALE;
        }
        #pragma unroll
        for (int j = 0; j < 4; j++) {
            int b = ent0 + 64 * j;
            float v[4] = {0.f, 0.f, 0.f, 0.f};
            #pragma unroll
            for (int i = 0; i < 8; i++) {
                float sg = ((b >> i) & 1) ? -1.f : 1.f;
                #pragma unroll
                for (int d = 0; d < 4; d++)
                    v[d] = fmaf(sg, t[d][i], v[d]);
            }
            s_tab[qd * TROW4 + b] = make_float4(v[0], v[1], v[2], v[3]);
        }
    }

    // ---- Stage sign bits via ballot: word w holds symbols 32w..32w+31
    // (local t <-> symbol g = q0-4+t; out-of-range -> +1, fixed up below).
    const int2* bits2 = (const int2*)(bits + (long long)row * NUM_BITS);
    const unsigned lane = tid & 31;
    #pragma unroll
    for (int k = 0; k < 3; k++) {
        int t = k * THREADS + tid;
        int g = q0 - 4 + t;
        bool valid = (t < SYMS_PER_BLOCK + 8) && (g >= 0) && (g < NS);
        int2 bb = make_int2(0, 0);
        if (valid) bb = bits2[g];
        unsigned mre = __ballot_sync(0xFFFFFFFFu, valid && (bb.y & 1));
        unsigned mim = __ballot_sync(0xFFFFFFFFu, valid && (bb.x & 1));
        int wi = t >> 5;
        if (lane == 0 && wi < NWORDS) { s_wre[wi] = mre; s_wim[wi] = mim; }
    }
    __syncthreads();

    // ---- Main loop: fixed phase quad (4l..4l+3) per thread.
    const int l    = tid & 3;
    const int grp  = tid >> 2;                 // 0..63 (symbol slot within step)
    const int flag = (l >= 2) ? 1 : 0;         // (phase >= 8)
    const float4* tabp = s_tab + l * TROW4;
    ulonglong2* out_base =
        out4 + (((long long)row * UP_LEN + (long long)tile * OUTS_PER_BLOCK) >> 1);

    #pragma unroll
    for (int it = 0; it < ITS; it++) {
        int s  = it * 64 + grp;                // symbol slot 0..511
        int w  = s + flag;                     // window start bit
        int wi = w >> 5, sh = w & 31;
        unsigned pre = __funnelshift_r(s_wre[wi], s_wre[wi + 1], sh) & 0xFF;
        unsigned pim = __funnelshift_r(s_wim[wi], s_wim[wi + 1], sh) & 0xFF;
        float4 vr = tabp[pre];                 // re for phases 4l..4l+3
        float4 vi = tabp[pim];                 // im for phases 4l..4l+3
        ulonglong2* dst = out_base + s * 8 + 2 * l;   // 4 consecutive complex
        stcs2(dst,     pack2(vr.x, vi.x), pack2(vr.y, vi.y));
        stcs2(dst + 1, pack2(vr.z, vi.z), pack2(vr.w, vi.w));
    }

    // ---- Edge fixup: windows touching symbols outside [0,NS) assumed +1;
    // true value uses 0. Contaminated: n<64 and n>=UP_LEN-64. Recompute.
    // Barrier orders fixup stores after mainloop stores (R8 lesson).
    if (tile == 0 || tile == TILES - 1) {
        __syncthreads();
        if (tid < 64) {
            int n = (tile == 0) ? tid : (UP_LEN - 64 + tid);
            int p = n & 15, q = n >> 4;
            int k0   = (71 - p) & 15;
            int jmin = (p <= 7) ? -4 : -3;
            float re = 0.f, im = 0.f;
            #pragma unroll
            for (int i = 0; i < 8; i++) {
                int g = q + jmin + i;
                if ((unsigned)g < (unsigned)NS) {
                    int2 bb = bits2[g];
                    float t = __ldg(rrc + k0 + 16 * i) * SCALE;
                    re += (bb.y & 1) ? -t : t;
                    im += (bb.x & 1) ? -t : t;
                }
            }
            ull* out2 = (ull*)out4;
            stcs1(out2 + (long long)row * UP_LEN + n, pack2(re, im));
        }
    }
}

extern "C" void kernel_launch(void* const* d_in, const int* in_sizes, int n_in,
                              void* d_out, int out_size)
{
    const int*   bits = (const int*)d_in[0];
    const float* rrc  = (const float*)d_in[1];
    ulonglong2*  out  = (ulonglong2*)d_out;

    dim3 grid(TILES, B_ROWS);                 // (16, 256)
    qpsk_mod_kernel<<<grid, THREADS>>>(bits, rrc, out);
}

// round 11
// speedup vs baseline: 2.3139x; 1.4449x over previous
#include <cuda_runtime.h>

// QPSK modulator: bits (256,16384) int32 -> Gray QPSK -> x16 zero-stuff
// (offset 8) -> RRC (K=128) -> out (256, 131072, 2) float32.
//
// Polyphase: y[16q+p] = sum_{i=0..7} sym[q+jmin+i] * rrc[k0+16i],
//   k0 = (71-p)&15, jmin = (p<=7) ? -4 : -3, scaled by sqrt(16).
// Symbols +-1/sqrt2 -> fold scale into taps -> each output is one of 256
// sums per phase -> 8x256 float2 table (even/odd phase) built per block.
// Mainloop: rolling sign-word pair (uint2, 1 LDS.64/iter) -> funnel-shift
// 8-bit patterns -> 2x LDS.64 table lookups -> coalesced streaming STG.128
// (consecutive lanes -> consecutive 16B; R9 lesson: stride kills the drain).
// R10 = R7 champion structure + packed rolling sign words.

#define B_ROWS     256
#define NUM_BITS   16384
#define NS         8192
#define SPS        16
#define UP_LEN     (NS * SPS)          // 131072
#define SCALE      2.82842712474619f   // sqrt(16)/sqrt(2)

#define SYMS_PER_BLOCK   512
#define OUTS_PER_BLOCK   (SYMS_PER_BLOCK * SPS)     // 8192 complex
#define THREADS          256
#define ITS              16
#define TILES            (UP_LEN / OUTS_PER_BLOCK)  // 16
#define TROW             257                        // padded row stride
#define NWORDS           18                         // 520 sign bits

typedef unsigned long long ull;

__device__ __forceinline__ ull pack2(float lo, float hi) {
    ull v;
    asm("mov.b64 %0, {%1, %2};" : "=l"(v) : "f"(lo), "f"(hi));
    return v;
}

__device__ __forceinline__ void stcs2(ulonglong2* p, ull lo, ull hi) {
    asm volatile("st.global.cs.v2.u64 [%0], {%1, %2};"
                 :: "l"(p), "l"(lo), "l"(hi) : "memory");
}

__device__ __forceinline__ void stcs1(ull* p, ull v) {
    asm volatile("st.global.cs.u64 [%0], %1;" :: "l"(p), "l"(v) : "memory");
}

__global__ __launch_bounds__(THREADS, 8)
void qpsk_mod_kernel(const int* __restrict__ bits,
                     const float* __restrict__ rrc,
                     ulonglong2* __restrict__ out4)
{
    __shared__ __align__(16) float2 s_tab[8 * TROW];
    __shared__ __align__(8) uint2 s_w[NWORDS];   // (re_word, im_word) packed

    const int tid  = threadIdx.x;
    const int tile = blockIdx.x;       // 0..15
    const int row  = blockIdx.y;       // 0..255
    const int q0   = tile * SYMS_PER_BLOCK;

    // ---- Build lookup table in-block: thread t fills row (t>>5), patterns
    // lane, lane+32, ..., lane+224. Taps load as warp-wide LDG broadcasts.
    {
        const int r    = tid >> 5;          // phase-pair row 0..7
        const int ln   = tid & 31;
        const int k0e  = (71 - 2 * r) & 15; // odd
        const int k0o  = k0e - 1;
        float te[8], to[8];
        #pragma unroll
        for (int i = 0; i < 8; i++) {
            te[i] = __ldg(rrc + k0e + 16 * i) * SCALE;
            to[i] = __ldg(rrc + k0o + 16 * i) * SCALE;
        }
        #pragma unroll
        for (int j = 0; j < 8; j++) {
            int b = ln + 32 * j;
            float se = 0.f, so = 0.f;
            #pragma unroll
            for (int i = 0; i < 8; i++) {
                float sg = ((b >> i) & 1) ? -1.f : 1.f;
                se = fmaf(sg, te[i], se);
                so = fmaf(sg, to[i], so);
            }
            s_tab[r * TROW + b] = make_float2(se, so);
        }
    }

    // ---- Stage sign bits via ballot: word w holds symbols 32w..32w+31
    // (local t <-> symbol g = q0-4+t; out-of-range -> +1, fixed up below).
    const int2* bits2 = (const int2*)(bits + (long long)row * NUM_BITS);
    const unsigned lane = tid & 31;
    #pragma unroll
    for (int k = 0; k < 3; k++) {
        int t = k * THREADS + tid;
        int g = q0 - 4 + t;
        bool valid = (t < SYMS_PER_BLOCK + 8) && (g >= 0) && (g < NS);
        int2 bb = make_int2(0, 0);
        if (valid) bb = bits2[g];
        unsigned mre = __ballot_sync(0xFFFFFFFFu, valid && (bb.y & 1));
        unsigned mim = __ballot_sync(0xFFFFFFFFu, valid && (bb.x & 1));
        int wi = t >> 5;
        if (lane == 0 && wi < NWORDS) s_w[wi] = make_uint2(mre, mim);
    }
    __syncthreads();

    // ---- Main loop: fixed phase pair (2l, 2l+1) per thread.
    // Window start w = it*32 + grp + flag -> wi = it + c, sh = const, where
    // c = (grp+flag)>>5 in {0,1}: word pairs roll forward one per iteration.
    const int l    = tid & 7;
    const int grp  = tid >> 3;                 // 0..31
    const int flag = (l >= 4) ? 1 : 0;         // (phase >= 8)
    const int wofs = grp + flag;               // 0..32
    const int c    = wofs >> 5;                // 0 or 1
    const int sh   = wofs & 31;
    const float2* tabp = s_tab + l * TROW;
    ulonglong2* out_base =
        out4 + (((long long)row * UP_LEN + (long long)tile * OUTS_PER_BLOCK) >> 1);

    uint2 wcur = s_w[c];                       // rolling current word pair
    #pragma unroll
    for (int it = 0; it < ITS; it++) {
        uint2 wnxt = s_w[it + c + 1];          // 1 LDS.64 per iteration
        unsigned pre = __funnelshift_r(wcur.x, wnxt.x, sh) & 0xFF;
        unsigned pim = __funnelshift_r(wcur.y, wnxt.y, sh) & 0xFF;
        float2 vr = tabp[pre];                 // (re_even, re_odd)
        float2 vi = tabp[pim];                 // (im_even, im_odd)
        int pi = it * THREADS + tid;           // consecutive lanes -> 16B apart
        stcs2(out_base + pi, pack2(vr.x, vi.x), pack2(vr.y, vi.y));
        wcur = wnxt;
    }

    // ---- Edge fixup: windows touching symbols outside [0,NS) assumed +1;
    // true value uses 0. Contaminated: n<64 and n>=UP_LEN-64. Recompute.
    // Barrier orders fixup stores after mainloop stores (R8 lesson).
    if (tile == 0 || tile == TILES - 1) {
        __syncthreads();
        if (tid < 64) {
            int n = (tile == 0) ? tid : (UP_LEN - 64 + tid);
            int p = n & 15, q = n >> 4;
            int k0   = (71 - p) & 15;
            int jmin = (p <= 7) ? -4 : -3;
            float re = 0.f, im = 0.f;
            #pragma unroll
            for (int i = 0; i < 8; i++) {
                int g = q + jmin + i;
                if ((unsigned)g < (unsigned)NS) {
                    int2 bb = bits2[g];
                    float t = __ldg(rrc + k0 + 16 * i) * SCALE;
                    re += (bb.y & 1) ? -t : t;
                    im += (bb.x & 1) ? -t : t;
                }
            }
            ull* out2 = (ull*)out4;
            stcs1(out2 + (long long)row * UP_LEN + n, pack2(re, im));
        }
    }
}

extern "C" void kernel_launch(void* const* d_in, const int* in_sizes, int n_in,
                              void* d_out, int out_size)
{
    const int*   bits = (const int*)d_in[0];
    const float* rrc  = (const float*)d_in[1];
    ulonglong2*  out  = (ulonglong2*)d_out;

    dim3 grid(TILES, B_ROWS);                 // (16, 256)
    qpsk_mod_kernel<<<grid, THREADS>>>(bits, rrc, out);
}

// round 13
// speedup vs baseline: 2.3835x; 1.0301x over previous
#include <cuda_runtime.h>

// QPSK modulator: bits (256,16384) int32 -> Gray QPSK -> x16 zero-stuff
// (offset 8) -> RRC (K=128) -> out (256, 131072, 2) float32.
//
// Polyphase: y[16q+p] = sum_{i=0..7} sym[q+jmin+i] * rrc[k0+16i],
//   k0 = (71-p)&15, jmin = (p<=7) ? -4 : -3, scaled by sqrt(16).
// Symbols +-1/sqrt2 -> each output is one of 256 signed-tap sums per phase
// -> 8x256 float2 table built per block; mainloop = ballot sign bits ->
// funnel-shift pattern -> 2x LDS.64 -> coalesced streaming STG.128.
//
// R13 = R7 champion + bits loads via createpolicy(L2::evict_last) +
// ld.global.nc.L2::cache_hint (R12's inline evict_last modifier is illegal
// on v2 loads per ptxas). Steady-state bench time is the DRAM drain of the
// 268MB output; pinning the 16MB input in L2 across graph replays removes
// the read share of DRAM bandwidth.

#define B_ROWS     256
#define NUM_BITS   16384
#define NS         8192
#define SPS        16
#define UP_LEN     (NS * SPS)          // 131072
#define SCALE      2.82842712474619f   // sqrt(16)/sqrt(2)

#define SYMS_PER_BLOCK   512
#define OUTS_PER_BLOCK   (SYMS_PER_BLOCK * SPS)     // 8192 complex
#define THREADS          256
#define ITS              16
#define TILES            (UP_LEN / OUTS_PER_BLOCK)  // 16
#define TROW             257                        // padded row stride
#define NWORDS           18                         // 520 sign bits

typedef unsigned long long ull;

__device__ __forceinline__ ull pack2(float lo, float hi) {
    ull v;
    asm("mov.b64 %0, {%1, %2};" : "=l"(v) : "f"(lo), "f"(hi));
    return v;
}

__device__ __forceinline__ void stcs2(ulonglong2* p, ull lo, ull hi) {
    asm volatile("st.global.cs.v2.u64 [%0], {%1, %2};"
                 :: "l"(p), "l"(lo), "l"(hi) : "memory");
}

__device__ __forceinline__ void stcs1(ull* p, ull v) {
    asm volatile("st.global.cs.u64 [%0], %1;" :: "l"(p), "l"(v) : "memory");
}

// bits load with L2 evict_last cache hint (pin input resident across replays)
__device__ __forceinline__ int2 ld_bits(const int2* p, ull pol) {
    int2 v;
    asm("ld.global.nc.L2::cache_hint.v2.u32 {%0, %1}, [%2], %3;"
        : "=r"(v.x), "=r"(v.y) : "l"(p), "l"(pol));
    return v;
}

__global__ __launch_bounds__(THREADS, 8)
void qpsk_mod_kernel(const int* __restrict__ bits,
                     const float* __restrict__ rrc,
                     ulonglong2* __restrict__ out4)
{
    __shared__ __align__(16) float2 s_tab[8 * TROW];
    __shared__ unsigned s_wre[NWORDS], s_wim[NWORDS];

    const int tid  = threadIdx.x;
    const int tile = blockIdx.x;       // 0..15
    const int row  = blockIdx.y;       // 0..255
    const int q0   = tile * SYMS_PER_BLOCK;

    ull pol;
    asm("createpolicy.fractional.L2::evict_last.b64 %0, 1.0;" : "=l"(pol));

    // ---- Build lookup table in-block: thread t fills row (t>>5), patterns
    // lane, lane+32, ..., lane+224. Taps load as warp-wide LDG broadcasts.
    {
        const int r    = tid >> 5;          // phase-pair row 0..7
        const int ln   = tid & 31;
        const int k0e  = (71 - 2 * r) & 15; // odd
        const int k0o  = k0e - 1;
        float te[8], to[8];
        #pragma unroll
        for (int i = 0; i < 8; i++) {
            te[i] = __ldg(rrc + k0e + 16 * i) * SCALE;
            to[i] = __ldg(rrc + k0o + 16 * i) * SCALE;
        }
        #pragma unroll
        for (int j = 0; j < 8; j++) {
            int b = ln + 32 * j;
            float se = 0.f, so = 0.f;
            #pragma unroll
            for (int i = 0; i < 8; i++) {
                float sg = ((b >> i) & 1) ? -1.f : 1.f;
                se = fmaf(sg, te[i], se);
                so = fmaf(sg, to[i], so);
            }
            s_tab[r * TROW + b] = make_float2(se, so);
        }
    }

    // ---- Stage sign bits via ballot: word w holds symbols 32w..32w+31
    // (local t <-> symbol g = q0-4+t; out-of-range -> +1, fixed up below).
    const int2* bits2 = (const int2*)(bits + (long long)row * NUM_BITS);
    const unsigned lane = tid & 31;
    #pragma unroll
    for (int k = 0; k < 3; k++) {
        int t = k * THREADS + tid;
        int g = q0 - 4 + t;
        bool valid = (t < SYMS_PER_BLOCK + 8) && (g >= 0) && (g < NS);
        int2 bb = make_int2(0, 0);
        if (valid) bb = ld_bits(bits2 + g, pol);
        unsigned mre = __ballot_sync(0xFFFFFFFFu, valid && (bb.y & 1));
        unsigned mim = __ballot_sync(0xFFFFFFFFu, valid && (bb.x & 1));
        int wi = t >> 5;
        if (lane == 0 && wi < NWORDS) { s_wre[wi] = mre; s_wim[wi] = mim; }
    }
    __syncthreads();

    // ---- Main loop: fixed phase pair (2l, 2l+1) per thread.
    const int l    = tid & 7;
    const int grp  = tid >> 3;                 // 0..31
    const int flag = (l >= 4) ? 1 : 0;         // (phase >= 8)
    const float2* tabp = s_tab + l * TROW;
    ulonglong2* out_base =
        out4 + (((long long)row * UP_LEN + (long long)tile * OUTS_PER_BLOCK) >> 1);

    #pragma unroll
    for (int it = 0; it < ITS; it++) {
        int pi = it * THREADS + tid;           // pair index 0..4095
        int w  = it * 32 + grp + flag;         // window start bit
        int wi = w >> 5, sh = w & 31;
        unsigned pre = __funnelshift_r(s_wre[wi], s_wre[wi + 1], sh) & 0xFF;
        unsigned pim = __funnelshift_r(s_wim[wi], s_wim[wi + 1], sh) & 0xFF;
        float2 vr = tabp[pre];                 // (re_even, re_odd)
        float2 vi = tabp[pim];                 // (im_even, im_odd)
        stcs2(out_base + pi, pack2(vr.x, vi.x), pack2(vr.y, vi.y));
    }

    // ---- Edge fixup: windows touching symbols outside [0,NS) assumed +1;
    // true value uses 0. Contaminated: n<64 and n>=UP_LEN-64. Recompute.
    // Barrier orders fixup stores after mainloop stores (R8 lesson).
    if (tile == 0 || tile == TILES - 1) {
        __syncthreads();
        if (tid < 64) {
            int n = (tile == 0) ? tid : (UP_LEN - 64 + tid);
            int p = n & 15, q = n >> 4;
            int k0   = (71 - p) & 15;
            int jmin = (p <= 7) ? -4 : -3;
            float re = 0.f, im = 0.f;
            #pragma unroll
            for (int i = 0; i < 8; i++) {
                int g = q + jmin + i;
                if ((unsigned)g < (unsigned)NS) {
                    int2 bb = ld_bits(bits2 + g, pol);
                    float t = __ldg(rrc + k0 + 16 * i) * SCALE;
                    re += (bb.y & 1) ? -t : t;
                    im += (bb.x & 1) ? -t : t;
                }
            }
            ull* out2 = (ull*)out4;
            stcs1(out2 + (long long)row * UP_LEN + n, pack2(re, im));
        }
    }
}

extern "C" void kernel_launch(void* const* d_in, const int* in_sizes, int n_in,
                              void* d_out, int out_size)
{
    const int*   bits = (const int*)d_in[0];
    const float* rrc  = (const float*)d_in[1];
    ulonglong2*  out  = (ulonglong2*)d_out;

    dim3 grid(TILES, B_ROWS);                 // (16, 256)
    qpsk_mod_kernel<<<grid, THREADS>>>(bits, rrc, out);
}